// round 1
// baseline (speedup 1.0000x reference)
#include <cuda_runtime.h>
#include <math.h>
#include <stdint.h>

#define HIDC 256
#define NHEAD 8
#define DHEAD 32
#define CLAMP_V 5.0f

static const int NMAXC = 50000;
static const int EMAXC = 320000;

// ---------------- scratch (single big static device buffer) ----------------
// offsets in floats
#define O_QH   ((size_t)0)
#define O_KH   (O_QH   + (size_t)NMAXC*HIDC)
#define O_VH   (O_KH   + (size_t)NMAXC*HIDC)
#define O_EW   (O_VH   + (size_t)NMAXC*HIDC)
#define O_EB   (O_EW   + (size_t)EMAXC*HIDC)
#define O_CA   (O_EB   + (size_t)EMAXC*HIDC)
#define O_OE   (O_CA   + (size_t)EMAXC*HIDC)
#define O_SC   (O_OE   + (size_t)EMAXC*HIDC)
#define O_SMAX (O_SC   + (size_t)EMAXC*NHEAD)
#define O_SSUM (O_SMAX + (size_t)NMAXC*NHEAD)
#define O_AGG  (O_SSUM + (size_t)NMAXC*NHEAD)
#define O_ROWV (O_AGG  + (size_t)NMAXC*HIDC)
#define O_ON   (O_ROWV + (size_t)NMAXC*HIDC)
#define O_H1   (O_ON   + (size_t)NMAXC*HIDC)
#define O_HLN  (O_H1   + (size_t)NMAXC*HIDC)
#define O_FFN  (O_HLN  + (size_t)NMAXC*HIDC)
#define O_H2   (O_FFN  + (size_t)NMAXC*2*HIDC)
#define O_TOTAL (O_H2  + (size_t)NMAXC*HIDC)

__device__ float g_scratch[O_TOTAL];

static inline int cdiv(int a, int b) { return (a + b - 1) / b; }

// ---------------- generic fp32 GEMM: C = A[M,K] @ B[K,Ncol] (+bias)(+resid)(relu) ----
// BM=128, BN=64, BK=16, 256 threads, each 8x4
template <int ACT>
__global__ void gemm_kernel(const float* __restrict__ A, const float* __restrict__ B,
                            const float* __restrict__ bias, const float* __restrict__ resid,
                            float* __restrict__ C, int M, int K, int Ncol) {
    __shared__ float As[128][17];
    __shared__ float Bs[16][64];

    const int tid = threadIdx.x;
    const int tx = tid & 15;   // col group
    const int ty = tid >> 4;   // row group
    const int m0 = blockIdx.x * 128;
    const int n0 = blockIdx.y * 64;

    float acc[8][4];
#pragma unroll
    for (int i = 0; i < 8; i++)
#pragma unroll
        for (int j = 0; j < 4; j++) acc[i][j] = 0.0f;

    const int ktiles = K >> 4;
    for (int kt = 0; kt < ktiles; kt++) {
        const int k0 = kt << 4;
        // load A tile: 128 rows x 16 cols
#pragma unroll
        for (int i = 0; i < 8; i++) {
            int e = tid + i * 256;
            int r = e >> 4, c = e & 15;
            int m = m0 + r;
            As[r][c] = (m < M) ? A[(size_t)m * K + k0 + c] : 0.0f;
        }
        // load B tile: 16 rows x 64 cols
#pragma unroll
        for (int i = 0; i < 4; i++) {
            int e = tid + i * 256;
            int r = e >> 6, c = e & 63;
            Bs[r][c] = B[(size_t)(k0 + r) * Ncol + n0 + c];
        }
        __syncthreads();
#pragma unroll
        for (int k = 0; k < 16; k++) {
            float4 b = *(const float4*)&Bs[k][tx * 4];
            float a[8];
#pragma unroll
            for (int i = 0; i < 8; i++) a[i] = As[ty * 8 + i][k];
#pragma unroll
            for (int i = 0; i < 8; i++) {
                acc[i][0] += a[i] * b.x;
                acc[i][1] += a[i] * b.y;
                acc[i][2] += a[i] * b.z;
                acc[i][3] += a[i] * b.w;
            }
        }
        __syncthreads();
    }

    float4 bv = make_float4(0.f, 0.f, 0.f, 0.f);
    if (bias) bv = *(const float4*)&bias[n0 + tx * 4];

#pragma unroll
    for (int i = 0; i < 8; i++) {
        int m = m0 + ty * 8 + i;
        if (m >= M) continue;
        float4 r;
        r.x = acc[i][0] + bv.x;
        r.y = acc[i][1] + bv.y;
        r.z = acc[i][2] + bv.z;
        r.w = acc[i][3] + bv.w;
        if (resid) {
            float4 rv = *(const float4*)&resid[(size_t)m * Ncol + n0 + tx * 4];
            r.x += rv.x; r.y += rv.y; r.z += rv.z; r.w += rv.w;
        }
        if (ACT == 1) {
            r.x = fmaxf(r.x, 0.f); r.y = fmaxf(r.y, 0.f);
            r.z = fmaxf(r.z, 0.f); r.w = fmaxf(r.w, 0.f);
        }
        *(float4*)&C[(size_t)m * Ncol + n0 + tx * 4] = r;
    }
}

// ---------------- LayerNorm: warp per row of 256 ----------------
__global__ void ln_kernel(const float* __restrict__ in, const float* __restrict__ g,
                          const float* __restrict__ b, float* __restrict__ out, int M) {
    int row = blockIdx.x * 8 + (threadIdx.x >> 5);
    int lane = threadIdx.x & 31;
    if (row >= M) return;
    const float* p = in + (size_t)row * HIDC;
    float v[8];
    float s = 0.f;
#pragma unroll
    for (int i = 0; i < 8; i++) { v[i] = p[lane + i * 32]; s += v[i]; }
#pragma unroll
    for (int o = 16; o > 0; o >>= 1) s += __shfl_xor_sync(0xffffffffu, s, o);
    float mean = s * (1.0f / HIDC);
    float vs = 0.f;
#pragma unroll
    for (int i = 0; i < 8; i++) { float d = v[i] - mean; vs += d * d; }
#pragma unroll
    for (int o = 16; o > 0; o >>= 1) vs += __shfl_xor_sync(0xffffffffu, vs, o);
    float rstd = rsqrtf(vs * (1.0f / HIDC) + 1e-5f);
    float* q = out + (size_t)row * HIDC;
#pragma unroll
    for (int i = 0; i < 8; i++) {
        int c = lane + i * 32;
        q[c] = (v[i] - mean) * rstd * g[c] + b[c];
    }
}

// ---------------- init: smax=-CLAMP, ssum=0, agg=0, rowv=0 ----------------
__global__ void init_kernel(float* agg, float* rowv, float* smax, float* ssum, int Nn) {
    int t = blockIdx.x * 256 + threadIdx.x;
    if (t < Nn * HIDC) { agg[t] = 0.f; rowv[t] = 0.f; }
    if (t < Nn * NHEAD) { smax[t] = -CLAMP_V; ssum[t] = 0.f; }
}

// ---------------- edge message: cA = relu(signsqrt((Qh[dst]+Kh[src])*Ew) + Eb) ----
__device__ __forceinline__ float edge_f(float a, float w, float b) {
    float c1 = a * w;
    float c2 = copysignf(sqrtf(fabsf(c1)), c1);
    return fmaxf(c2 + b, 0.f);
}

__global__ void edge_msg_kernel(const float* __restrict__ Qh, const float* __restrict__ Kh,
                                const float* __restrict__ Ew, const float* __restrict__ Eb,
                                float* __restrict__ cA, const int* __restrict__ dst,
                                const int* __restrict__ src, int E) {
    long t = (long)blockIdx.x * 256 + threadIdx.x;
    if (t >= (long)E * 64) return;
    int e = (int)(t >> 6), q = (int)(t & 63);
    int dn = dst[e], sn = src[e];
    float4 qv = *(const float4*)&Qh[(size_t)dn * HIDC + q * 4];
    float4 kv = *(const float4*)&Kh[(size_t)sn * HIDC + q * 4];
    float4 ew = *(const float4*)&Ew[(size_t)e * HIDC + q * 4];
    float4 eb = *(const float4*)&Eb[(size_t)e * HIDC + q * 4];
    float4 r;
    r.x = edge_f(qv.x + kv.x, ew.x, eb.x);
    r.y = edge_f(qv.y + kv.y, ew.y, eb.y);
    r.z = edge_f(qv.z + kv.z, ew.z, eb.z);
    r.w = edge_f(qv.w + kv.w, ew.w, eb.w);
    *(float4*)&cA[(size_t)e * HIDC + q * 4] = r;
}

// ---------------- score + segment max ----------------
__device__ __forceinline__ void atomicMaxF(float* addr, float val) {
    int* ai = (int*)addr;
    int old = *ai;
    while (__int_as_float(old) < val) {
        int assumed = old;
        old = atomicCAS(ai, assumed, __float_as_int(val));
        if (old == assumed) break;
    }
}

__global__ void score_kernel(const float* __restrict__ Oe, const float* __restrict__ Aw,
                             float* __restrict__ score, float* __restrict__ smax,
                             const int* __restrict__ dst, int E) {
    int t = blockIdx.x * 256 + threadIdx.x;
    if (t >= E * NHEAD) return;
    int e = t >> 3, h = t & 7;
    const float4* op = (const float4*)(Oe + (size_t)e * HIDC + h * DHEAD);
    float s = 0.f;
#pragma unroll
    for (int d4 = 0; d4 < 8; d4++) {
        float4 o = op[d4];
        int d = d4 * 4;
        s += o.x * __ldg(&Aw[d * 8 + h]) + o.y * __ldg(&Aw[(d + 1) * 8 + h]) +
             o.z * __ldg(&Aw[(d + 2) * 8 + h]) + o.w * __ldg(&Aw[(d + 3) * 8 + h]);
    }
    s = fminf(fmaxf(s, -CLAMP_V), CLAMP_V);
    score[t] = s;
    atomicMaxF(&smax[dst[e] * NHEAD + h], s);
}

// ---------------- exp + segment sum (score buffer overwritten with ex) ----------------
__global__ void ex_kernel(float* __restrict__ score, const float* __restrict__ smax,
                          float* __restrict__ ssum, const int* __restrict__ dst, int E) {
    int t = blockIdx.x * 256 + threadIdx.x;
    if (t >= E * NHEAD) return;
    int e = t >> 3, h = t & 7;
    int dn = dst[e];
    float ex = expf(score[t] - smax[dn * NHEAD + h]);
    score[t] = ex;
    atomicAdd(&ssum[dn * NHEAD + h], ex);
}

// ---------------- scatter: agg += Vh[src]*sc, rowv += Oe*sc ----------------
__global__ void scatter_kernel(const float* __restrict__ exv, const float* __restrict__ ssum,
                               const float* __restrict__ Vh, const float* __restrict__ Oe,
                               float* __restrict__ agg, float* __restrict__ rowv,
                               const int* __restrict__ dst, const int* __restrict__ src, int E) {
    long t = (long)blockIdx.x * 256 + threadIdx.x;
    if (t >= (long)E * 64) return;
    int e = (int)(t >> 6), q = (int)(t & 63);
    int h = q >> 3;
    int dn = dst[e], sn = src[e];
    float sc = exv[e * NHEAD + h] / (ssum[dn * NHEAD + h] + 1e-16f);
    float4 v = *(const float4*)&Vh[(size_t)sn * HIDC + q * 4];
    float4 o = *(const float4*)&Oe[(size_t)e * HIDC + q * 4];
    float* ap = &agg[(size_t)dn * HIDC + q * 4];
    atomicAdd(ap + 0, v.x * sc); atomicAdd(ap + 1, v.y * sc);
    atomicAdd(ap + 2, v.z * sc); atomicAdd(ap + 3, v.w * sc);
    float* rp = &rowv[(size_t)dn * HIDC + q * 4];
    atomicAdd(rp + 0, o.x * sc); atomicAdd(rp + 1, o.y * sc);
    atomicAdd(rp + 2, o.z * sc); atomicAdd(rp + 3, o.w * sc);
}

// ---------------- combine: On = agg + einsum(rowv, BW) ----------------
__global__ void combine_kernel(const float* __restrict__ agg, const float* __restrict__ rowv,
                               const float* __restrict__ BW, float* __restrict__ On, int Nn) {
    __shared__ float sBW[DHEAD * NHEAD * DHEAD];  // 8192 floats, 32KB
    __shared__ float srv[HIDC];
    int tid = threadIdx.x;
    for (int i = tid; i < DHEAD * NHEAD * DHEAD; i += 256) sBW[i] = BW[i];
    int h = tid >> 5, c = tid & 31;
    for (int r = 0; r < 4; r++) {
        int n = blockIdx.x * 4 + r;
        __syncthreads();
        if (n < Nn) srv[tid] = rowv[(size_t)n * HIDC + tid];
        __syncthreads();
        if (n < Nn) {
            float s = agg[(size_t)n * HIDC + tid];
#pragma unroll
            for (int d = 0; d < DHEAD; d++)
                s += srv[h * DHEAD + d] * sBW[d * HIDC + h * DHEAD + c];
            On[(size_t)n * HIDC + tid] = s;
        }
    }
}

// ---------------- launch ----------------
extern "C" void kernel_launch(void* const* d_in, const int* in_sizes, int n_in,
                              void* d_out, int out_size) {
    const float* x     = (const float*)d_in[0];
    const float* conn  = (const float*)d_in[1];
    const float* Wq    = (const float*)d_in[2];
    const float* Wk    = (const float*)d_in[3];
    const float* Wv    = (const float*)d_in[4];
    const float* Wew   = (const float*)d_in[5];
    const float* Web   = (const float*)d_in[6];
    const float* beb   = (const float*)d_in[7];
    const float* Weo   = (const float*)d_in[8];
    const float* beo   = (const float*)d_in[9];
    const float* Aw    = (const float*)d_in[10];
    const float* BW    = (const float*)d_in[11];
    const float* Wo_h  = (const float*)d_in[12];
    const float* bo_h  = (const float*)d_in[13];
    const float* Wo_e  = (const float*)d_in[14];
    const float* bo_e  = (const float*)d_in[15];
    const float* ln1hg = (const float*)d_in[16];
    const float* ln1hb = (const float*)d_in[17];
    const float* ln1eg = (const float*)d_in[18];
    const float* ln1eb = (const float*)d_in[19];
    const float* W1    = (const float*)d_in[20];
    const float* b1    = (const float*)d_in[21];
    const float* W2    = (const float*)d_in[22];
    const float* b2    = (const float*)d_in[23];
    const float* ln2hg = (const float*)d_in[24];
    const float* ln2hb = (const float*)d_in[25];
    const int*   ei    = (const int*)d_in[26];

    int Nn = in_sizes[0] / HIDC;
    int Ee = in_sizes[26] / 2;
    const int* dst = ei;
    const int* src = ei + Ee;

    float* S = nullptr;
    cudaGetSymbolAddress((void**)&S, g_scratch);

    float* Qh   = S + O_QH;
    float* Kh   = S + O_KH;
    float* Vh   = S + O_VH;
    float* Ew   = S + O_EW;
    float* Eb   = S + O_EB;
    float* cA   = S + O_CA;
    float* Oe   = S + O_OE;
    float* sc   = S + O_SC;
    float* smax = S + O_SMAX;
    float* ssum = S + O_SSUM;
    float* agg  = S + O_AGG;
    float* rowv = S + O_ROWV;
    float* On   = S + O_ON;
    float* h1   = S + O_H1;
    float* hln  = S + O_HLN;
    float* ffn  = S + O_FFN;
    float* h2   = S + O_H2;

    float* outH = (float*)d_out;
    float* outE = outH + (size_t)Nn * HIDC;

    // init scatter buffers early
    init_kernel<<<cdiv(Nn * HIDC, 256), 256>>>(agg, rowv, smax, ssum, Nn);

    // node / edge projections
    {
        dim3 g(cdiv(Nn, 128), HIDC / 64);
        gemm_kernel<0><<<g, 256>>>(x, Wq, nullptr, nullptr, Qh, Nn, HIDC, HIDC);
        gemm_kernel<0><<<g, 256>>>(x, Wk, nullptr, nullptr, Kh, Nn, HIDC, HIDC);
        gemm_kernel<0><<<g, 256>>>(x, Wv, nullptr, nullptr, Vh, Nn, HIDC, HIDC);
    }
    {
        dim3 g(cdiv(Ee, 128), HIDC / 64);
        gemm_kernel<0><<<g, 256>>>(conn, Wew, nullptr, nullptr, Ew, Ee, HIDC, HIDC);
        gemm_kernel<0><<<g, 256>>>(conn, Web, beb, nullptr, Eb, Ee, HIDC, HIDC);
    }

    // edge messages
    edge_msg_kernel<<<cdiv(Ee * 64, 256), 256>>>(Qh, Kh, Ew, Eb, cA, dst, src, Ee);

    // Oe = cA @ Weo + beo
    {
        dim3 g(cdiv(Ee, 128), HIDC / 64);
        gemm_kernel<0><<<g, 256>>>(cA, Weo, beo, nullptr, Oe, Ee, HIDC, HIDC);
    }

    // attention scores + scatter softmax
    score_kernel<<<cdiv(Ee * NHEAD, 256), 256>>>(Oe, Aw, sc, smax, dst, Ee);
    ex_kernel<<<cdiv(Ee * NHEAD, 256), 256>>>(sc, smax, ssum, dst, Ee);
    scatter_kernel<<<cdiv(Ee * 64, 256), 256>>>(sc, ssum, Vh, Oe, agg, rowv, dst, src, Ee);

    // combine: On = agg + rowv @ BW (per head)
    combine_kernel<<<cdiv(Nn, 4), 256>>>(agg, rowv, BW, On, Nn);

    // h path: h = LN1h(x + On @ Wo_h + bo_h)
    {
        dim3 g(cdiv(Nn, 128), HIDC / 64);
        gemm_kernel<0><<<g, 256>>>(On, Wo_h, bo_h, x, h1, Nn, HIDC, HIDC);
    }
    ln_kernel<<<cdiv(Nn, 8), 256>>>(h1, ln1hg, ln1hb, hln, Nn);

    // e path: e_out = LN1e(conn + Oe @ Wo_e + bo_e)  (reuse cA as temp)
    {
        dim3 g(cdiv(Ee, 128), HIDC / 64);
        gemm_kernel<0><<<g, 256>>>(Oe, Wo_e, bo_e, conn, cA, Ee, HIDC, HIDC);
    }
    ln_kernel<<<cdiv(Ee, 8), 256>>>(cA, ln1eg, ln1eb, outE, Ee);

    // FFN: h_out = LN2h(hln + relu(hln @ W1 + b1) @ W2 + b2)
    {
        dim3 g(cdiv(Nn, 128), (2 * HIDC) / 64);
        gemm_kernel<1><<<g, 256>>>(hln, W1, b1, nullptr, ffn, Nn, HIDC, 2 * HIDC);
    }
    {
        dim3 g(cdiv(Nn, 128), HIDC / 64);
        gemm_kernel<0><<<g, 256>>>(ffn, W2, b2, hln, h2, Nn, 2 * HIDC, HIDC);
    }
    ln_kernel<<<cdiv(Nn, 8), 256>>>(h2, ln2hg, ln2hb, outH, Nn);
}

// round 2
// speedup vs baseline: 2.4401x; 2.4401x over previous
#include <cuda_runtime.h>
#include <math.h>
#include <stdint.h>

#define HIDC 256
#define NHEAD 8
#define DHEAD 32
#define CLAMP_V 5.0f

static const int NMAXC = 50000;
static const int EMAXC = 320000;

// ---------------- scratch ----------------
#define O_QH   ((size_t)0)
#define O_KH   (O_QH   + (size_t)NMAXC*HIDC)
#define O_VH   (O_KH   + (size_t)NMAXC*HIDC)
#define O_EW   (O_VH   + (size_t)NMAXC*HIDC)
#define O_EB   (O_EW   + (size_t)EMAXC*HIDC)
#define O_CA   (O_EB   + (size_t)EMAXC*HIDC)
#define O_OE   (O_CA   + (size_t)EMAXC*HIDC)
#define O_SC   (O_OE   + (size_t)EMAXC*HIDC)
#define O_SMAX (O_SC   + (size_t)EMAXC*NHEAD)
#define O_SSUM (O_SMAX + (size_t)NMAXC*NHEAD)
#define O_AGG  (O_SSUM + (size_t)NMAXC*NHEAD)
#define O_ROWV (O_AGG  + (size_t)NMAXC*HIDC)
#define O_ON   (O_ROWV + (size_t)NMAXC*HIDC)
#define O_H1   (O_ON   + (size_t)NMAXC*HIDC)
#define O_HLN  (O_H1   + (size_t)NMAXC*HIDC)
#define O_FFN  (O_HLN  + (size_t)NMAXC*HIDC)
#define O_H2   (O_FFN  + (size_t)NMAXC*2*HIDC)
#define O_TOTAL (O_H2  + (size_t)NMAXC*HIDC)

__device__ float g_scratch[O_TOTAL];

static inline int cdiv(int a, int b) { return (a + b - 1) / b; }

// ---------------- tf32 helpers ----------------
__device__ __forceinline__ uint32_t f2tf32(float f) {
    uint32_t r;
    asm("cvt.rna.tf32.f32 %0, %1;" : "=r"(r) : "f"(f));
    return r;
}

__device__ __forceinline__ void mma_tf32(float c[4], const uint32_t a[4], const uint32_t b[2]) {
    asm volatile(
        "mma.sync.aligned.m16n8k8.row.col.f32.tf32.tf32.f32 "
        "{%0,%1,%2,%3}, {%4,%5,%6,%7}, {%8,%9}, {%0,%1,%2,%3};"
        : "+f"(c[0]), "+f"(c[1]), "+f"(c[2]), "+f"(c[3])
        : "r"(a[0]), "r"(a[1]), "r"(a[2]), "r"(a[3]), "r"(b[0]), "r"(b[1]));
}

// ---------------- tensor-core tf32 GEMM ----------------
// C[M,N] = A[M,K] @ B[K,N] (+bias)(+resid)(relu)
// BM=128, BN=128, BK=16, 256 threads = 8 warps (4 m-warps x 2 n-warps),
// warp tile 32x64 = 2 m16 x 8 n8 mma tiles. Double-buffered smem, reg-staged
// prefetch with cvt.rna fp32->tf32 at the STS stage.
#define SA 20    // A smem row stride (floats): conflict-free fragment reads
#define SB 136   // B smem row stride

template <int ACT>
__global__ __launch_bounds__(256, 2)
void gemm_tc(const float* __restrict__ A, const float* __restrict__ B,
             const float* __restrict__ bias, const float* __restrict__ resid,
             float* __restrict__ C, int M, int K, int N) {
    __shared__ uint32_t As[2][128 * SA];
    __shared__ uint32_t Bs[2][16 * SB];

    const int tid = threadIdx.x;
    const int warp = tid >> 5;
    const int lane = tid & 31;
    const int g = lane >> 2;     // groupID
    const int t = lane & 3;      // threadID_in_group
    const int warp_m = warp & 3; // 4 warps over M (32 rows each)
    const int warp_n = warp >> 2;// 2 warps over N (64 cols each)
    const int m0 = blockIdx.x * 128;
    const int n0 = blockIdx.y * 128;

    float acc[2][8][4];
#pragma unroll
    for (int i = 0; i < 2; i++)
#pragma unroll
        for (int j = 0; j < 8; j++)
#pragma unroll
            for (int q = 0; q < 4; q++) acc[i][j][q] = 0.0f;

    const int KT = K >> 4;

    float4 a4[2], b4[2];

    // ---- prologue: load tile 0 into regs, store to buf 0 ----
    {
        const int k0 = 0;
#pragma unroll
        for (int u = 0; u < 2; u++) {
            int f = tid + u * 256;
            int ar = f >> 2, ac4 = f & 3;
            int m = m0 + ar;
            a4[u] = (m < M) ? *(const float4*)&A[(size_t)m * K + k0 + ac4 * 4]
                            : make_float4(0.f, 0.f, 0.f, 0.f);
            int br = f >> 5, bc4 = f & 31;
            b4[u] = *(const float4*)&B[(size_t)(k0 + br) * N + n0 + bc4 * 4];
        }
#pragma unroll
        for (int u = 0; u < 2; u++) {
            int f = tid + u * 256;
            int ar = f >> 2, ac4 = f & 3;
            uint32_t* d = &As[0][ar * SA + ac4 * 4];
            d[0] = f2tf32(a4[u].x); d[1] = f2tf32(a4[u].y);
            d[2] = f2tf32(a4[u].z); d[3] = f2tf32(a4[u].w);
            int br = f >> 5, bc4 = f & 31;
            uint32_t* db = &Bs[0][br * SB + bc4 * 4];
            db[0] = f2tf32(b4[u].x); db[1] = f2tf32(b4[u].y);
            db[2] = f2tf32(b4[u].z); db[3] = f2tf32(b4[u].w);
        }
    }
    __syncthreads();

    for (int kt = 0; kt < KT; kt++) {
        const int cur = kt & 1;

        // prefetch next tile into regs
        if (kt + 1 < KT) {
            const int k0 = (kt + 1) << 4;
#pragma unroll
            for (int u = 0; u < 2; u++) {
                int f = tid + u * 256;
                int ar = f >> 2, ac4 = f & 3;
                int m = m0 + ar;
                a4[u] = (m < M) ? *(const float4*)&A[(size_t)m * K + k0 + ac4 * 4]
                                : make_float4(0.f, 0.f, 0.f, 0.f);
                int br = f >> 5, bc4 = f & 31;
                b4[u] = *(const float4*)&B[(size_t)(k0 + br) * N + n0 + bc4 * 4];
            }
        }

        // compute on current buffer
#pragma unroll
        for (int ks = 0; ks < 2; ks++) {
            const int kk = ks * 8;
            uint32_t af[2][4];
#pragma unroll
            for (int i = 0; i < 2; i++) {
                int rm = warp_m * 32 + i * 16 + g;
                af[i][0] = As[cur][rm * SA + kk + t];
                af[i][1] = As[cur][(rm + 8) * SA + kk + t];
                af[i][2] = As[cur][rm * SA + kk + t + 4];
                af[i][3] = As[cur][(rm + 8) * SA + kk + t + 4];
            }
            uint32_t bf[8][2];
#pragma unroll
            for (int j = 0; j < 8; j++) {
                int cn = warp_n * 64 + j * 8 + g;
                bf[j][0] = Bs[cur][(kk + t) * SB + cn];
                bf[j][1] = Bs[cur][(kk + t + 4) * SB + cn];
            }
#pragma unroll
            for (int i = 0; i < 2; i++)
#pragma unroll
                for (int j = 0; j < 8; j++)
                    mma_tf32(acc[i][j], af[i], bf[j]);
        }

        // stage next tile into alternate buffer
        if (kt + 1 < KT) {
#pragma unroll
            for (int u = 0; u < 2; u++) {
                int f = tid + u * 256;
                int ar = f >> 2, ac4 = f & 3;
                uint32_t* d = &As[cur ^ 1][ar * SA + ac4 * 4];
                d[0] = f2tf32(a4[u].x); d[1] = f2tf32(a4[u].y);
                d[2] = f2tf32(a4[u].z); d[3] = f2tf32(a4[u].w);
                int br = f >> 5, bc4 = f & 31;
                uint32_t* db = &Bs[cur ^ 1][br * SB + bc4 * 4];
                db[0] = f2tf32(b4[u].x); db[1] = f2tf32(b4[u].y);
                db[2] = f2tf32(b4[u].z); db[3] = f2tf32(b4[u].w);
            }
        }
        __syncthreads();
    }

    // ---- epilogue ----
#pragma unroll
    for (int j = 0; j < 8; j++) {
        int c = n0 + warp_n * 64 + j * 8 + 2 * t;
        float2 bv = make_float2(0.f, 0.f);
        if (bias) bv = *(const float2*)&bias[c];
#pragma unroll
        for (int i = 0; i < 2; i++) {
            int rbase = m0 + warp_m * 32 + i * 16 + g;
#pragma unroll
            for (int half = 0; half < 2; half++) {
                int r = rbase + half * 8;
                if (r >= M) continue;
                float2 o;
                o.x = acc[i][j][half * 2 + 0] + bv.x;
                o.y = acc[i][j][half * 2 + 1] + bv.y;
                if (resid) {
                    float2 rv = *(const float2*)&resid[(size_t)r * N + c];
                    o.x += rv.x; o.y += rv.y;
                }
                if (ACT == 1) { o.x = fmaxf(o.x, 0.f); o.y = fmaxf(o.y, 0.f); }
                *(float2*)&C[(size_t)r * N + c] = o;
            }
        }
    }
}

// ---------------- LayerNorm: warp per row of 256 ----------------
__global__ void ln_kernel(const float* __restrict__ in, const float* __restrict__ g,
                          const float* __restrict__ b, float* __restrict__ out, int M) {
    int row = blockIdx.x * 8 + (threadIdx.x >> 5);
    int lane = threadIdx.x & 31;
    if (row >= M) return;
    const float* p = in + (size_t)row * HIDC;
    float v[8];
    float s = 0.f;
#pragma unroll
    for (int i = 0; i < 8; i++) { v[i] = p[lane + i * 32]; s += v[i]; }
#pragma unroll
    for (int o = 16; o > 0; o >>= 1) s += __shfl_xor_sync(0xffffffffu, s, o);
    float mean = s * (1.0f / HIDC);
    float vs = 0.f;
#pragma unroll
    for (int i = 0; i < 8; i++) { float d = v[i] - mean; vs += d * d; }
#pragma unroll
    for (int o = 16; o > 0; o >>= 1) vs += __shfl_xor_sync(0xffffffffu, vs, o);
    float rstd = rsqrtf(vs * (1.0f / HIDC) + 1e-5f);
    float* q = out + (size_t)row * HIDC;
#pragma unroll
    for (int i = 0; i < 8; i++) {
        int c = lane + i * 32;
        q[c] = (v[i] - mean) * rstd * g[c] + b[c];
    }
}

// ---------------- init ----------------
__global__ void init_kernel(float* agg, float* rowv, float* smax, float* ssum, int Nn) {
    int t = blockIdx.x * 256 + threadIdx.x;
    if (t < Nn * HIDC) { agg[t] = 0.f; rowv[t] = 0.f; }
    if (t < Nn * NHEAD) { smax[t] = -CLAMP_V; ssum[t] = 0.f; }
}

// ---------------- edge message ----------------
__device__ __forceinline__ float edge_f(float a, float w, float b) {
    float c1 = a * w;
    float c2 = copysignf(sqrtf(fabsf(c1)), c1);
    return fmaxf(c2 + b, 0.f);
}

__global__ void edge_msg_kernel(const float* __restrict__ Qh, const float* __restrict__ Kh,
                                const float* __restrict__ Ew, const float* __restrict__ Eb,
                                float* __restrict__ cA, const int* __restrict__ dst,
                                const int* __restrict__ src, int E) {
    long t = (long)blockIdx.x * 256 + threadIdx.x;
    if (t >= (long)E * 64) return;
    int e = (int)(t >> 6), q = (int)(t & 63);
    int dn = dst[e], sn = src[e];
    float4 qv = *(const float4*)&Qh[(size_t)dn * HIDC + q * 4];
    float4 kv = *(const float4*)&Kh[(size_t)sn * HIDC + q * 4];
    float4 ew = *(const float4*)&Ew[(size_t)e * HIDC + q * 4];
    float4 eb = *(const float4*)&Eb[(size_t)e * HIDC + q * 4];
    float4 r;
    r.x = edge_f(qv.x + kv.x, ew.x, eb.x);
    r.y = edge_f(qv.y + kv.y, ew.y, eb.y);
    r.z = edge_f(qv.z + kv.z, ew.z, eb.z);
    r.w = edge_f(qv.w + kv.w, ew.w, eb.w);
    *(float4*)&cA[(size_t)e * HIDC + q * 4] = r;
}

// ---------------- score + segment max ----------------
__device__ __forceinline__ void atomicMaxF(float* addr, float val) {
    int* ai = (int*)addr;
    int old = *ai;
    while (__int_as_float(old) < val) {
        int assumed = old;
        old = atomicCAS(ai, assumed, __float_as_int(val));
        if (old == assumed) break;
    }
}

__global__ void score_kernel(const float* __restrict__ Oe, const float* __restrict__ Aw,
                             float* __restrict__ score, float* __restrict__ smax,
                             const int* __restrict__ dst, int E) {
    int t = blockIdx.x * 256 + threadIdx.x;
    if (t >= E * NHEAD) return;
    int e = t >> 3, h = t & 7;
    const float4* op = (const float4*)(Oe + (size_t)e * HIDC + h * DHEAD);
    float s = 0.f;
#pragma unroll
    for (int d4 = 0; d4 < 8; d4++) {
        float4 o = op[d4];
        int d = d4 * 4;
        s += o.x * __ldg(&Aw[d * 8 + h]) + o.y * __ldg(&Aw[(d + 1) * 8 + h]) +
             o.z * __ldg(&Aw[(d + 2) * 8 + h]) + o.w * __ldg(&Aw[(d + 3) * 8 + h]);
    }
    s = fminf(fmaxf(s, -CLAMP_V), CLAMP_V);
    score[t] = s;
    atomicMaxF(&smax[dst[e] * NHEAD + h], s);
}

// ---------------- exp + segment sum ----------------
__global__ void ex_kernel(float* __restrict__ score, const float* __restrict__ smax,
                          float* __restrict__ ssum, const int* __restrict__ dst, int E) {
    int t = blockIdx.x * 256 + threadIdx.x;
    if (t >= E * NHEAD) return;
    int e = t >> 3, h = t & 7;
    int dn = dst[e];
    float ex = expf(score[t] - smax[dn * NHEAD + h]);
    score[t] = ex;
    atomicAdd(&ssum[dn * NHEAD + h], ex);
}

// ---------------- scatter ----------------
__global__ void scatter_kernel(const float* __restrict__ exv, const float* __restrict__ ssum,
                               const float* __restrict__ Vh, const float* __restrict__ Oe,
                               float* __restrict__ agg, float* __restrict__ rowv,
                               const int* __restrict__ dst, const int* __restrict__ src, int E) {
    long t = (long)blockIdx.x * 256 + threadIdx.x;
    if (t >= (long)E * 64) return;
    int e = (int)(t >> 6), q = (int)(t & 63);
    int h = q >> 3;
    int dn = dst[e], sn = src[e];
    float sc = exv[e * NHEAD + h] / (ssum[dn * NHEAD + h] + 1e-16f);
    float4 v = *(const float4*)&Vh[(size_t)sn * HIDC + q * 4];
    float4 o = *(const float4*)&Oe[(size_t)e * HIDC + q * 4];
    float* ap = &agg[(size_t)dn * HIDC + q * 4];
    atomicAdd(ap + 0, v.x * sc); atomicAdd(ap + 1, v.y * sc);
    atomicAdd(ap + 2, v.z * sc); atomicAdd(ap + 3, v.w * sc);
    float* rp = &rowv[(size_t)dn * HIDC + q * 4];
    atomicAdd(rp + 0, o.x * sc); atomicAdd(rp + 1, o.y * sc);
    atomicAdd(rp + 2, o.z * sc); atomicAdd(rp + 3, o.w * sc);
}

// ---------------- combine ----------------
__global__ void combine_kernel(const float* __restrict__ agg, const float* __restrict__ rowv,
                               const float* __restrict__ BW, float* __restrict__ On, int Nn) {
    __shared__ float sBW[DHEAD * NHEAD * DHEAD];
    __shared__ float srv[HIDC];
    int tid = threadIdx.x;
    for (int i = tid; i < DHEAD * NHEAD * DHEAD; i += 256) sBW[i] = BW[i];
    int h = tid >> 5, c = tid & 31;
    for (int r = 0; r < 4; r++) {
        int n = blockIdx.x * 4 + r;
        __syncthreads();
        if (n < Nn) srv[tid] = rowv[(size_t)n * HIDC + tid];
        __syncthreads();
        if (n < Nn) {
            float s = agg[(size_t)n * HIDC + tid];
#pragma unroll
            for (int d = 0; d < DHEAD; d++)
                s += srv[h * DHEAD + d] * sBW[d * HIDC + h * DHEAD + c];
            On[(size_t)n * HIDC + tid] = s;
        }
    }
}

// ---------------- launch ----------------
extern "C" void kernel_launch(void* const* d_in, const int* in_sizes, int n_in,
                              void* d_out, int out_size) {
    const float* x     = (const float*)d_in[0];
    const float* conn  = (const float*)d_in[1];
    const float* Wq    = (const float*)d_in[2];
    const float* Wk    = (const float*)d_in[3];
    const float* Wv    = (const float*)d_in[4];
    const float* Wew   = (const float*)d_in[5];
    const float* Web   = (const float*)d_in[6];
    const float* beb   = (const float*)d_in[7];
    const float* Weo   = (const float*)d_in[8];
    const float* beo   = (const float*)d_in[9];
    const float* Aw    = (const float*)d_in[10];
    const float* BW    = (const float*)d_in[11];
    const float* Wo_h  = (const float*)d_in[12];
    const float* bo_h  = (const float*)d_in[13];
    const float* Wo_e  = (const float*)d_in[14];
    const float* bo_e  = (const float*)d_in[15];
    const float* ln1hg = (const float*)d_in[16];
    const float* ln1hb = (const float*)d_in[17];
    const float* ln1eg = (const float*)d_in[18];
    const float* ln1eb = (const float*)d_in[19];
    const float* W1    = (const float*)d_in[20];
    const float* b1    = (const float*)d_in[21];
    const float* W2    = (const float*)d_in[22];
    const float* b2    = (const float*)d_in[23];
    const float* ln2hg = (const float*)d_in[24];
    const float* ln2hb = (const float*)d_in[25];
    const int*   ei    = (const int*)d_in[26];

    int Nn = in_sizes[0] / HIDC;
    int Ee = in_sizes[26] / 2;
    const int* dst = ei;
    const int* src = ei + Ee;

    float* S = nullptr;
    cudaGetSymbolAddress((void**)&S, g_scratch);

    float* Qh   = S + O_QH;
    float* Kh   = S + O_KH;
    float* Vh   = S + O_VH;
    float* Ew   = S + O_EW;
    float* Eb   = S + O_EB;
    float* cA   = S + O_CA;
    float* Oe   = S + O_OE;
    float* sc   = S + O_SC;
    float* smax = S + O_SMAX;
    float* ssum = S + O_SSUM;
    float* agg  = S + O_AGG;
    float* rowv = S + O_ROWV;
    float* On   = S + O_ON;
    float* h1   = S + O_H1;
    float* hln  = S + O_HLN;
    float* ffn  = S + O_FFN;
    float* h2   = S + O_H2;

    float* outH = (float*)d_out;
    float* outE = outH + (size_t)Nn * HIDC;

    init_kernel<<<cdiv(Nn * HIDC, 256), 256>>>(agg, rowv, smax, ssum, Nn);

    // node projections
    {
        dim3 g(cdiv(Nn, 128), HIDC / 128);
        gemm_tc<0><<<g, 256>>>(x, Wq, nullptr, nullptr, Qh, Nn, HIDC, HIDC);
        gemm_tc<0><<<g, 256>>>(x, Wk, nullptr, nullptr, Kh, Nn, HIDC, HIDC);
        gemm_tc<0><<<g, 256>>>(x, Wv, nullptr, nullptr, Vh, Nn, HIDC, HIDC);
    }
    // edge projections
    {
        dim3 g(cdiv(Ee, 128), HIDC / 128);
        gemm_tc<0><<<g, 256>>>(conn, Wew, nullptr, nullptr, Ew, Ee, HIDC, HIDC);
        gemm_tc<0><<<g, 256>>>(conn, Web, beb, nullptr, Eb, Ee, HIDC, HIDC);
    }

    edge_msg_kernel<<<cdiv(Ee * 64, 256), 256>>>(Qh, Kh, Ew, Eb, cA, dst, src, Ee);

    {
        dim3 g(cdiv(Ee, 128), HIDC / 128);
        gemm_tc<0><<<g, 256>>>(cA, Weo, beo, nullptr, Oe, Ee, HIDC, HIDC);
    }

    score_kernel<<<cdiv(Ee * NHEAD, 256), 256>>>(Oe, Aw, sc, smax, dst, Ee);
    ex_kernel<<<cdiv(Ee * NHEAD, 256), 256>>>(sc, smax, ssum, dst, Ee);
    scatter_kernel<<<cdiv(Ee * 64, 256), 256>>>(sc, ssum, Vh, Oe, agg, rowv, dst, src, Ee);

    combine_kernel<<<cdiv(Nn, 4), 256>>>(agg, rowv, BW, On, Nn);

    // h path
    {
        dim3 g(cdiv(Nn, 128), HIDC / 128);
        gemm_tc<0><<<g, 256>>>(On, Wo_h, bo_h, x, h1, Nn, HIDC, HIDC);
    }
    ln_kernel<<<cdiv(Nn, 8), 256>>>(h1, ln1hg, ln1hb, hln, Nn);

    // e path
    {
        dim3 g(cdiv(Ee, 128), HIDC / 128);
        gemm_tc<0><<<g, 256>>>(Oe, Wo_e, bo_e, conn, cA, Ee, HIDC, HIDC);
    }
    ln_kernel<<<cdiv(Ee, 8), 256>>>(cA, ln1eg, ln1eb, outE, Ee);

    // FFN
    {
        dim3 g(cdiv(Nn, 128), (2 * HIDC) / 128);
        gemm_tc<1><<<g, 256>>>(hln, W1, b1, nullptr, ffn, Nn, HIDC, 2 * HIDC);
    }
    {
        dim3 g(cdiv(Nn, 128), HIDC / 128);
        gemm_tc<0><<<g, 256>>>(ffn, W2, b2, hln, h2, Nn, 2 * HIDC, HIDC);
    }
    ln_kernel<<<cdiv(Nn, 8), 256>>>(h2, ln2hg, ln2hb, outH, Nn);
}

// round 3
// speedup vs baseline: 2.7972x; 1.1464x over previous
#include <cuda_runtime.h>
#include <math.h>
#include <stdint.h>

#define HIDC 256
#define NHEAD 8
#define CLAMP_V 5.0f

static const int NMAXC = 50000;
static const int EMAXC = 320000;

// ---------------- scratch layout (floats) ----------------
#define O_QKV  ((size_t)0)                          // N*768
#define O_CA   (O_QKV  + (size_t)NMAXC*768)         // E*256
#define O_OE   (O_CA   + (size_t)EMAXC*256)         // E*256
#define O_SCB  (O_OE   + (size_t)EMAXC*256)         // E*8
#define O_SMAX (O_SCB  + (size_t)EMAXC*8)           // N*8
#define O_SSUM (O_SMAX + (size_t)NMAXC*8)           // N*8
#define O_AGG  (O_SSUM + (size_t)NMAXC*8)           // N*256
#define O_ROWV (O_AGG  + (size_t)NMAXC*256)         // N*256
#define O_ON   (O_ROWV + (size_t)NMAXC*256)         // N*256
#define O_H1   (O_ON   + (size_t)NMAXC*256)         // N*256
#define O_HLN  (O_H1   + (size_t)NMAXC*256)         // N*256
#define O_HLNT (O_HLN  + (size_t)NMAXC*256)         // N*256
#define O_FFN  (O_HLNT + (size_t)NMAXC*256)         // N*512
#define O_H2   (O_FFN  + (size_t)NMAXC*512)         // N*256
#define O_XT   (O_H2   + (size_t)NMAXC*256)         // N*256
#define O_CT   (O_XT   + (size_t)NMAXC*256)         // E*256
#define O_WQKV (O_CT   + (size_t)EMAXC*256)         // 256*768
#define O_WEWB (O_WQKV + (size_t)256*768)           // 256*512
#define O_WEO  (O_WEWB + (size_t)256*512)           // 256*256
#define O_WOH  (O_WEO  + (size_t)256*256)           // 256*256
#define O_WOE  (O_WOH  + (size_t)256*256)           // 256*256
#define O_W1   (O_WOE  + (size_t)256*256)           // 256*512
#define O_W2   (O_W1   + (size_t)256*512)           // 512*256
#define O_TOTAL (O_W2  + (size_t)512*256)

__device__ float g_scratch[O_TOTAL];

static inline int cdiv(int a, int b) { return (a + b - 1) / b; }

// ---------------- tf32 helpers ----------------
__device__ __forceinline__ float tf32r(float f) {
    uint32_t r;
    asm("cvt.rna.tf32.f32 %0, %1;" : "=r"(r) : "f"(f));
    return __uint_as_float(r);
}

__device__ __forceinline__ void mma_tf32(float c[4], const uint32_t a[4], const uint32_t b[2]) {
    asm volatile(
        "mma.sync.aligned.m16n8k8.row.col.f32.tf32.tf32.f32 "
        "{%0,%1,%2,%3}, {%4,%5,%6,%7}, {%8,%9}, {%0,%1,%2,%3};"
        : "+f"(c[0]), "+f"(c[1]), "+f"(c[2]), "+f"(c[3])
        : "r"(a[0]), "r"(a[1]), "r"(a[2]), "r"(a[3]), "r"(b[0]), "r"(b[1]));
}

__device__ __forceinline__ void cp16(uint32_t saddr, const float* g, bool pred) {
    int sz = pred ? 16 : 0;
    asm volatile("cp.async.ca.shared.global [%0], [%1], 16, %2;\n"
                 :: "r"(saddr), "l"(g), "r"(sz));
}
#define CP_COMMIT() asm volatile("cp.async.commit_group;\n" ::)
#define CP_WAIT(n)  asm volatile("cp.async.wait_group %0;\n" :: "n"(n))

// ---------------- tensor-core tf32 GEMM ----------------
// A,B assumed already tf32-rounded fp32 bit patterns. BM=128, BN=128, BK=32,
// 256 thr = 8 warps (4m x 2n), warp tile 32x64. cp.async double-buffered.
// ACT: 0 = bias?+resid?+store, 1 = bias+relu+store, 2 = fused edge message
// CVT: round output to tf32 before store (for GEMM-consumed outputs)
#define ASZ (128 * 36)
#define BSZ (32 * 136)
#define GEMM_SMEM ((2 * ASZ + 2 * BSZ) * 4)

template <int ACT, int CVT>
__global__ __launch_bounds__(256, 2)
void gemm_tc(const float* __restrict__ A, const float* __restrict__ B,
             const float* __restrict__ bias, const float* __restrict__ resid,
             float* __restrict__ C, int M, int K, int N,
             const int* __restrict__ dst, const int* __restrict__ src,
             const float* __restrict__ QKV) {
    extern __shared__ float sm[];
    float* Asm = sm;
    float* Bsm = sm + 2 * ASZ;

    const int tid = threadIdx.x;
    const int warp = tid >> 5;
    const int lane = tid & 31;
    const int g = lane >> 2;
    const int t = lane & 3;
    const int warp_m = warp & 3;
    const int warp_n = warp >> 2;
    const int m0 = blockIdx.x * 128;
    const int n0 = blockIdx.y * 128;

    const uint32_t sbase = (uint32_t)__cvta_generic_to_shared(sm);
    const uint32_t bbase = sbase + 2 * ASZ * 4;

    // staging indices
    const int arow = tid >> 3;         // + u*32
    const int ac = (tid & 7) * 4;
    const int brow = tid >> 5;         // + u*8
    const int bc = (tid & 31) * 4;

    float acc[2][8][4];
#pragma unroll
    for (int i = 0; i < 2; i++)
#pragma unroll
        for (int j = 0; j < 8; j++)
#pragma unroll
            for (int q = 0; q < 4; q++) acc[i][j][q] = 0.0f;

    const int KT = K >> 5;

    // prologue: stage tile 0 into buffer 0
    {
#pragma unroll
        for (int u = 0; u < 4; u++) {
            int r = arow + u * 32;
            cp16(sbase + (r * 36 + ac) * 4, A + (size_t)(m0 + r) * K + ac, (m0 + r) < M);
        }
#pragma unroll
        for (int u = 0; u < 4; u++) {
            int r = brow + u * 8;
            cp16(bbase + (r * 136 + bc) * 4, B + (size_t)r * N + n0 + bc, true);
        }
        CP_COMMIT();
    }

    for (int kt = 0; kt < KT; kt++) {
        const int buf = kt & 1;
        if (kt + 1 < KT) {
            const int k0 = (kt + 1) << 5;
            const int nb = buf ^ 1;
#pragma unroll
            for (int u = 0; u < 4; u++) {
                int r = arow + u * 32;
                cp16(sbase + (nb * ASZ + r * 36 + ac) * 4,
                     A + (size_t)(m0 + r) * K + k0 + ac, (m0 + r) < M);
            }
#pragma unroll
            for (int u = 0; u < 4; u++) {
                int r = brow + u * 8;
                cp16(bbase + (nb * BSZ + r * 136 + bc) * 4,
                     B + (size_t)(k0 + r) * N + n0 + bc, true);
            }
            CP_COMMIT();
            CP_WAIT(1);
        } else {
            CP_WAIT(0);
        }
        __syncthreads();

        const uint32_t* Ab = (const uint32_t*)(Asm + buf * ASZ);
        const uint32_t* Bb = (const uint32_t*)(Bsm + buf * BSZ);

#pragma unroll
        for (int ks = 0; ks < 4; ks++) {
            const int kk = ks * 8;
            uint32_t af[2][4];
#pragma unroll
            for (int i = 0; i < 2; i++) {
                int rm = warp_m * 32 + i * 16 + g;
                af[i][0] = Ab[rm * 36 + kk + t];
                af[i][1] = Ab[(rm + 8) * 36 + kk + t];
                af[i][2] = Ab[rm * 36 + kk + t + 4];
                af[i][3] = Ab[(rm + 8) * 36 + kk + t + 4];
            }
            uint32_t bf[8][2];
#pragma unroll
            for (int j = 0; j < 8; j++) {
                int cn = warp_n * 64 + j * 8 + g;
                bf[j][0] = Bb[(kk + t) * 136 + cn];
                bf[j][1] = Bb[(kk + t + 4) * 136 + cn];
            }
#pragma unroll
            for (int i = 0; i < 2; i++)
#pragma unroll
                for (int j = 0; j < 8; j++)
                    mma_tf32(acc[i][j], af[i], bf[j]);
        }
        __syncthreads();
    }

    // ---- epilogue ----
    if (ACT == 2) {
        // fused edge message: acc pairs (even,odd) = (Ew, Eb) for output col c>>1
        float bebv[8];
        int cqv[8];
#pragma unroll
        for (int j = 0; j < 8; j++) {
            int cq = (n0 >> 1) + warp_n * 32 + j * 4 + t;
            cqv[j] = cq;
            bebv[j] = bias[cq];  // bias = beb
        }
#pragma unroll
        for (int i = 0; i < 2; i++) {
#pragma unroll
            for (int half = 0; half < 2; half++) {
                int r = m0 + warp_m * 32 + i * 16 + half * 8 + g;
                if (r >= M) continue;
                int dn = dst[r], sn = src[r];
                const float* qrow = QKV + (size_t)dn * 768;
                const float* krow = QKV + (size_t)sn * 768 + 256;
#pragma unroll
                for (int j = 0; j < 8; j++) {
                    float ew = acc[i][j][half * 2 + 0];
                    float eb = acc[i][j][half * 2 + 1] + bebv[j];
                    float aqk = qrow[cqv[j]] + krow[cqv[j]];
                    float c1 = aqk * ew;
                    float c2 = copysignf(sqrtf(fabsf(c1)), c1);
                    float v = fmaxf(c2 + eb, 0.f);
                    C[(size_t)r * 256 + cqv[j]] = tf32r(v);
                }
            }
        }
    } else {
#pragma unroll
        for (int j = 0; j < 8; j++) {
            int c = n0 + warp_n * 64 + j * 8 + 2 * t;
            float2 bv = make_float2(0.f, 0.f);
            if (bias) bv = *(const float2*)&bias[c];
#pragma unroll
            for (int i = 0; i < 2; i++) {
                int rbase = m0 + warp_m * 32 + i * 16 + g;
#pragma unroll
                for (int half = 0; half < 2; half++) {
                    int r = rbase + half * 8;
                    if (r >= M) continue;
                    float2 o;
                    o.x = acc[i][j][half * 2 + 0] + bv.x;
                    o.y = acc[i][j][half * 2 + 1] + bv.y;
                    if (resid) {
                        float2 rv = *(const float2*)&resid[(size_t)r * N + c];
                        o.x += rv.x; o.y += rv.y;
                    }
                    if (ACT == 1) { o.x = fmaxf(o.x, 0.f); o.y = fmaxf(o.y, 0.f); }
                    if (CVT == 1) { o.x = tf32r(o.x); o.y = tf32r(o.y); }
                    *(float2*)&C[(size_t)r * N + c] = o;
                }
            }
        }
    }
}

// ---------------- weight pack: concat / interleave + tf32 round ----------------
__global__ void pack_kernel(const float* Wq, const float* Wk, const float* Wv,
                            const float* Wew, const float* Web, const float* Weo,
                            const float* Wo_h, const float* Wo_e,
                            const float* W1, const float* W2, float* S) {
    int i = blockIdx.x * 256 + threadIdx.x;
    float* wqkv = S + O_WQKV;
    float* wewb = S + O_WEWB;
    float* weo = S + O_WEO;
    float* woh = S + O_WOH;
    float* woe = S + O_WOE;
    float* w1 = S + O_W1;
    float* w2 = S + O_W2;
    if (i < 196608) {  // Wqkv [256][768]
        int k = i / 768, j = i % 768;
        float v = (j < 256) ? Wq[k * 256 + j]
                : (j < 512) ? Wk[k * 256 + j - 256]
                            : Wv[k * 256 + j - 512];
        wqkv[i] = tf32r(v);
    }
    int i2 = i - 196608;
    if (i2 >= 0 && i2 < 131072) {  // Wewb [256][512] interleaved
        int k = i2 / 512, j = i2 % 512, c = j >> 1;
        float v = (j & 1) ? Web[k * 256 + c] : Wew[k * 256 + c];
        wewb[i2] = tf32r(v);
    }
    int i3 = i - 327680;
    if (i3 >= 0 && i3 < 65536) weo[i3] = tf32r(Weo[i3]);
    int i4 = i - 393216;
    if (i4 >= 0 && i4 < 65536) woh[i4] = tf32r(Wo_h[i4]);
    int i5 = i - 458752;
    if (i5 >= 0 && i5 < 65536) woe[i5] = tf32r(Wo_e[i5]);
    int i6 = i - 524288;
    if (i6 >= 0 && i6 < 131072) w1[i6] = tf32r(W1[i6]);
    int i7 = i - 655360;
    if (i7 >= 0 && i7 < 131072) w2[i7] = tf32r(W2[i7]);
}

// ---------------- tf32-round copy (float4) ----------------
__global__ void cvt_kernel(const float* __restrict__ in, float* __restrict__ out, long n4) {
    long i = (long)blockIdx.x * 256 + threadIdx.x;
    if (i >= n4) return;
    float4 v = ((const float4*)in)[i];
    v.x = tf32r(v.x); v.y = tf32r(v.y); v.z = tf32r(v.z); v.w = tf32r(v.w);
    ((float4*)out)[i] = v;
}

// ---------------- LayerNorm (optional second tf32 output) ----------------
__global__ void ln_kernel(const float* __restrict__ in, const float* __restrict__ g,
                          const float* __restrict__ b, float* __restrict__ out,
                          float* __restrict__ out_t, int M) {
    int row = blockIdx.x * 8 + (threadIdx.x >> 5);
    int lane = threadIdx.x & 31;
    if (row >= M) return;
    const float* p = in + (size_t)row * HIDC;
    float v[8];
    float s = 0.f;
#pragma unroll
    for (int i = 0; i < 8; i++) { v[i] = p[lane + i * 32]; s += v[i]; }
#pragma unroll
    for (int o = 16; o > 0; o >>= 1) s += __shfl_xor_sync(0xffffffffu, s, o);
    float mean = s * (1.0f / HIDC);
    float vs = 0.f;
#pragma unroll
    for (int i = 0; i < 8; i++) { float d = v[i] - mean; vs += d * d; }
#pragma unroll
    for (int o = 16; o > 0; o >>= 1) vs += __shfl_xor_sync(0xffffffffu, vs, o);
    float rstd = rsqrtf(vs * (1.0f / HIDC) + 1e-5f);
    float* q = out + (size_t)row * HIDC;
    float* qt = out_t ? out_t + (size_t)row * HIDC : nullptr;
#pragma unroll
    for (int i = 0; i < 8; i++) {
        int c = lane + i * 32;
        float val = (v[i] - mean) * rstd * g[c] + b[c];
        q[c] = val;
        if (qt) qt[c] = tf32r(val);
    }
}

// ---------------- init ----------------
__global__ void init_kernel(float* agg, float* rowv, float* smax, float* ssum, int Nn) {
    int t = blockIdx.x * 256 + threadIdx.x;
    if (t < Nn * HIDC) { agg[t] = 0.f; rowv[t] = 0.f; }
    if (t < Nn * NHEAD) { smax[t] = -CLAMP_V; ssum[t] = 0.f; }
}

// ---------------- score + segment max ----------------
__device__ __forceinline__ void atomicMaxF(float* addr, float val) {
    int* ai = (int*)addr;
    int old = *ai;
    while (__int_as_float(old) < val) {
        int assumed = old;
        old = atomicCAS(ai, assumed, __float_as_int(val));
        if (old == assumed) break;
    }
}

__global__ void score_kernel(const float* __restrict__ Oe, const float* __restrict__ Aw,
                             float* __restrict__ score, float* __restrict__ smax,
                             const int* __restrict__ dst, int E) {
    int t = blockIdx.x * 256 + threadIdx.x;
    if (t >= E * NHEAD) return;
    int e = t >> 3, h = t & 7;
    const float4* op = (const float4*)(Oe + (size_t)e * HIDC + h * 32);
    float s = 0.f;
#pragma unroll
    for (int d4 = 0; d4 < 8; d4++) {
        float4 o = op[d4];
        int d = d4 * 4;
        s += o.x * __ldg(&Aw[d * 8 + h]) + o.y * __ldg(&Aw[(d + 1) * 8 + h]) +
             o.z * __ldg(&Aw[(d + 2) * 8 + h]) + o.w * __ldg(&Aw[(d + 3) * 8 + h]);
    }
    s = fminf(fmaxf(s, -CLAMP_V), CLAMP_V);
    score[t] = s;
    atomicMaxF(&smax[dst[e] * NHEAD + h], s);
}

// ---------------- exp + segment sum ----------------
__global__ void ex_kernel(float* __restrict__ score, const float* __restrict__ smax,
                          float* __restrict__ ssum, const int* __restrict__ dst, int E) {
    int t = blockIdx.x * 256 + threadIdx.x;
    if (t >= E * NHEAD) return;
    int e = t >> 3, h = t & 7;
    int dn = dst[e];
    float ex = expf(score[t] - smax[dn * NHEAD + h]);
    score[t] = ex;
    atomicAdd(&ssum[dn * NHEAD + h], ex);
}

// ---------------- scatter (V rows live in QKV at col offset 512, stride 768) ----
__global__ void scatter_kernel(const float* __restrict__ exv, const float* __restrict__ ssum,
                               const float* __restrict__ QKV, const float* __restrict__ Oe,
                               float* __restrict__ agg, float* __restrict__ rowv,
                               const int* __restrict__ dst, const int* __restrict__ src, int E) {
    long t = (long)blockIdx.x * 256 + threadIdx.x;
    if (t >= (long)E * 64) return;
    int e = (int)(t >> 6), q = (int)(t & 63);
    int h = q >> 3;
    int dn = dst[e], sn = src[e];
    float sc = exv[e * NHEAD + h] / (ssum[dn * NHEAD + h] + 1e-16f);
    float4 v = *(const float4*)&QKV[(size_t)sn * 768 + 512 + q * 4];
    float4 o = *(const float4*)&Oe[(size_t)e * HIDC + q * 4];
    float* ap = &agg[(size_t)dn * HIDC + q * 4];
    atomicAdd(ap + 0, v.x * sc); atomicAdd(ap + 1, v.y * sc);
    atomicAdd(ap + 2, v.z * sc); atomicAdd(ap + 3, v.w * sc);
    float* rp = &rowv[(size_t)dn * HIDC + q * 4];
    atomicAdd(rp + 0, o.x * sc); atomicAdd(rp + 1, o.y * sc);
    atomicAdd(rp + 2, o.z * sc); atomicAdd(rp + 3, o.w * sc);
}

// ---------------- combine: On = tf32(agg + einsum(rowv, BW)) ----------------
__global__ void combine_kernel(const float* __restrict__ agg, const float* __restrict__ rowv,
                               const float* __restrict__ BW, float* __restrict__ On, int Nn) {
    __shared__ float sBW[32 * 8 * 32];
    __shared__ float srv[HIDC];
    int tid = threadIdx.x;
    for (int i = tid; i < 32 * 8 * 32; i += 256) sBW[i] = BW[i];
    int h = tid >> 5, c = tid & 31;
    for (int r = 0; r < 4; r++) {
        int n = blockIdx.x * 4 + r;
        __syncthreads();
        if (n < Nn) srv[tid] = rowv[(size_t)n * HIDC + tid];
        __syncthreads();
        if (n < Nn) {
            float s = agg[(size_t)n * HIDC + tid];
#pragma unroll
            for (int d = 0; d < 32; d++)
                s += srv[h * 32 + d] * sBW[d * HIDC + h * 32 + c];
            On[(size_t)n * HIDC + tid] = tf32r(s);
        }
    }
}

// ---------------- launch ----------------
extern "C" void kernel_launch(void* const* d_in, const int* in_sizes, int n_in,
                              void* d_out, int out_size) {
    const float* x     = (const float*)d_in[0];
    const float* conn  = (const float*)d_in[1];
    const float* Wq    = (const float*)d_in[2];
    const float* Wk    = (const float*)d_in[3];
    const float* Wv    = (const float*)d_in[4];
    const float* Wew   = (const float*)d_in[5];
    const float* Web   = (const float*)d_in[6];
    const float* beb   = (const float*)d_in[7];
    const float* Weo   = (const float*)d_in[8];
    const float* beo   = (const float*)d_in[9];
    const float* Aw    = (const float*)d_in[10];
    const float* BW    = (const float*)d_in[11];
    const float* Wo_h  = (const float*)d_in[12];
    const float* bo_h  = (const float*)d_in[13];
    const float* Wo_e  = (const float*)d_in[14];
    const float* bo_e  = (const float*)d_in[15];
    const float* ln1hg = (const float*)d_in[16];
    const float* ln1hb = (const float*)d_in[17];
    const float* ln1eg = (const float*)d_in[18];
    const float* ln1eb = (const float*)d_in[19];
    const float* W1    = (const float*)d_in[20];
    const float* b1    = (const float*)d_in[21];
    const float* W2    = (const float*)d_in[22];
    const float* b2    = (const float*)d_in[23];
    const float* ln2hg = (const float*)d_in[24];
    const float* ln2hb = (const float*)d_in[25];
    const int*   ei    = (const int*)d_in[26];

    int Nn = in_sizes[0] / HIDC;
    int Ee = in_sizes[26] / 2;
    const int* dst = ei;
    const int* src = ei + Ee;

    float* S = nullptr;
    cudaGetSymbolAddress((void**)&S, g_scratch);

    float* QKV  = S + O_QKV;
    float* cA   = S + O_CA;
    float* Oe   = S + O_OE;
    float* scb  = S + O_SCB;
    float* smax = S + O_SMAX;
    float* ssum = S + O_SSUM;
    float* agg  = S + O_AGG;
    float* rowv = S + O_ROWV;
    float* On   = S + O_ON;
    float* h1   = S + O_H1;
    float* hln  = S + O_HLN;
    float* hlnt = S + O_HLNT;
    float* ffn  = S + O_FFN;
    float* h2   = S + O_H2;
    float* xt   = S + O_XT;
    float* ct   = S + O_CT;

    float* outH = (float*)d_out;
    float* outE = outH + (size_t)Nn * HIDC;

    // opt into >48KB dynamic smem (idempotent; runs on capture)
    cudaFuncSetAttribute(gemm_tc<0, 0>, cudaFuncAttributeMaxDynamicSharedMemorySize, GEMM_SMEM);
    cudaFuncSetAttribute(gemm_tc<0, 1>, cudaFuncAttributeMaxDynamicSharedMemorySize, GEMM_SMEM);
    cudaFuncSetAttribute(gemm_tc<1, 1>, cudaFuncAttributeMaxDynamicSharedMemorySize, GEMM_SMEM);
    cudaFuncSetAttribute(gemm_tc<2, 0>, cudaFuncAttributeMaxDynamicSharedMemorySize, GEMM_SMEM);

    // prep: pack weights, round inputs, init scatter buffers
    pack_kernel<<<cdiv(786432, 256), 256>>>(Wq, Wk, Wv, Wew, Web, Weo, Wo_h, Wo_e, W1, W2, S);
    cvt_kernel<<<cdiv(Nn * 64, 256), 256>>>(x, xt, (long)Nn * 64);
    cvt_kernel<<<(int)cdiv((long)Ee * 64, 256), 256>>>(conn, ct, (long)Ee * 64);
    init_kernel<<<cdiv(Nn * HIDC, 256), 256>>>(agg, rowv, smax, ssum, Nn);

    // QKV = xt @ Wqkv   [N, 768]
    {
        dim3 g(cdiv(Nn, 128), 6);
        gemm_tc<0, 0><<<g, 256, GEMM_SMEM>>>(xt, S + O_WQKV, nullptr, nullptr, QKV,
                                             Nn, 256, 768, nullptr, nullptr, nullptr);
    }
    // fused: EwEb GEMM + edge message -> cA (tf32)
    {
        dim3 g(cdiv(Ee, 128), 4);
        gemm_tc<2, 0><<<g, 256, GEMM_SMEM>>>(ct, S + O_WEWB, beb, nullptr, cA,
                                             Ee, 256, 512, dst, src, QKV);
    }
    // Oe = cA @ Weo + beo (tf32 out)
    {
        dim3 g(cdiv(Ee, 128), 2);
        gemm_tc<0, 1><<<g, 256, GEMM_SMEM>>>(cA, S + O_WEO, beo, nullptr, Oe,
                                             Ee, 256, 256, nullptr, nullptr, nullptr);
    }

    score_kernel<<<cdiv(Ee * NHEAD, 256), 256>>>(Oe, Aw, scb, smax, dst, Ee);
    ex_kernel<<<cdiv(Ee * NHEAD, 256), 256>>>(scb, smax, ssum, dst, Ee);
    scatter_kernel<<<(int)cdiv((long)Ee * 64, 256), 256>>>(scb, ssum, QKV, Oe, agg, rowv, dst, src, Ee);
    combine_kernel<<<cdiv(Nn, 4), 256>>>(agg, rowv, BW, On, Nn);

    // h path: h1 = x + On @ Wo_h + bo_h ; hln = LN1h(h1) (+ tf32 copy)
    {
        dim3 g(cdiv(Nn, 128), 2);
        gemm_tc<0, 0><<<g, 256, GEMM_SMEM>>>(On, S + O_WOH, bo_h, x, h1,
                                             Nn, 256, 256, nullptr, nullptr, nullptr);
    }
    ln_kernel<<<cdiv(Nn, 8), 256>>>(h1, ln1hg, ln1hb, hln, hlnt, Nn);

    // e path: outE = LN1e(conn + Oe @ Wo_e + bo_e)   (reuse cA as temp)
    {
        dim3 g(cdiv(Ee, 128), 2);
        gemm_tc<0, 0><<<g, 256, GEMM_SMEM>>>(Oe, S + O_WOE, bo_e, conn, cA,
                                             Ee, 256, 256, nullptr, nullptr, nullptr);
    }
    ln_kernel<<<cdiv(Ee, 8), 256>>>(cA, ln1eg, ln1eb, outE, nullptr, Ee);

    // FFN: ffn = relu(hlnt @ W1 + b1) (tf32) ; h2 = hln + ffn @ W2 + b2
    {
        dim3 g(cdiv(Nn, 128), 4);
        gemm_tc<1, 1><<<g, 256, GEMM_SMEM>>>(hlnt, S + O_W1, b1, nullptr, ffn,
                                             Nn, 256, 512, nullptr, nullptr, nullptr);
    }
    {
        dim3 g(cdiv(Nn, 128), 2);
        gemm_tc<0, 0><<<g, 256, GEMM_SMEM>>>(ffn, S + O_W2, b2, hln, h2,
                                             Nn, 512, 256, nullptr, nullptr, nullptr);
    }
    ln_kernel<<<cdiv(Nn, 8), 256>>>(h2, ln2hg, ln2hb, outH, nullptr, Nn);
}

// round 5
// speedup vs baseline: 2.9249x; 1.0456x over previous
#include <cuda_runtime.h>
#include <math.h>
#include <stdint.h>

#define HIDC 256
#define NHEAD 8
#define CLAMP_V 5.0f

static const int NMAXC = 50000;
static const int EMAXC = 320000;

// ---------------- scratch layout (floats) ----------------
#define O_QKV  ((size_t)0)                          // N*768
#define O_CA   (O_QKV  + (size_t)NMAXC*768)         // E*256
#define O_OE   (O_CA   + (size_t)EMAXC*256)         // E*256
#define O_SCB  (O_OE   + (size_t)EMAXC*256)         // E*8
#define O_SMAX (O_SCB  + (size_t)EMAXC*8)           // N*8
#define O_SSUM (O_SMAX + (size_t)NMAXC*8)           // N*8
#define O_AGG  (O_SSUM + (size_t)NMAXC*8)           // N*256
#define O_ROWV (O_AGG  + (size_t)NMAXC*256)         // N*256
#define O_ON   (O_ROWV + (size_t)NMAXC*256)         // N*256
#define O_H1   (O_ON   + (size_t)NMAXC*256)         // N*256
#define O_HLN  (O_H1   + (size_t)NMAXC*256)         // N*256
#define O_HLNT (O_HLN  + (size_t)NMAXC*256)         // N*256
#define O_FFN  (O_HLNT + (size_t)NMAXC*256)         // N*512
#define O_H2   (O_FFN  + (size_t)NMAXC*512)         // N*256
#define O_XT   (O_H2   + (size_t)NMAXC*256)         // N*256
#define O_CT   (O_XT   + (size_t)NMAXC*256)         // E*256
#define O_WQKV (O_CT   + (size_t)EMAXC*256)         // 768*256 (transposed [N][K])
#define O_WEWB (O_WQKV + (size_t)768*256)           // 512*256
#define O_WEO  (O_WEWB + (size_t)512*256)           // 256*256
#define O_WOH  (O_WEO  + (size_t)256*256)           // 256*256
#define O_WOE  (O_WOH  + (size_t)256*256)           // 256*256
#define O_W1   (O_WOE  + (size_t)256*256)           // 512*256
#define O_W2   (O_W1   + (size_t)512*256)           // 256*512
#define O_TOTAL (O_W2  + (size_t)256*512)

__device__ float g_scratch[O_TOTAL];

static inline int cdiv(int a, int b) { return (a + b - 1) / b; }

// ---------------- tf32 helpers ----------------
__device__ __forceinline__ float tf32r(float f) {
    uint32_t r;
    asm("cvt.rna.tf32.f32 %0, %1;" : "=r"(r) : "f"(f));
    return __uint_as_float(r);
}

__device__ __forceinline__ void mma_tf32(float c[4], const uint32_t a[4], const uint32_t b[2]) {
    asm volatile(
        "mma.sync.aligned.m16n8k8.row.col.f32.tf32.tf32.f32 "
        "{%0,%1,%2,%3}, {%4,%5,%6,%7}, {%8,%9}, {%0,%1,%2,%3};"
        : "+f"(c[0]), "+f"(c[1]), "+f"(c[2]), "+f"(c[3])
        : "r"(a[0]), "r"(a[1]), "r"(a[2]), "r"(a[3]), "r"(b[0]), "r"(b[1]));
}

__device__ __forceinline__ void ldsm4(uint32_t& r0, uint32_t& r1, uint32_t& r2, uint32_t& r3,
                                      uint32_t addr) {
    asm volatile("ldmatrix.sync.aligned.m8n8.x4.shared.b16 {%0,%1,%2,%3}, [%4];"
                 : "=r"(r0), "=r"(r1), "=r"(r2), "=r"(r3) : "r"(addr));
}

__device__ __forceinline__ void cp16(uint32_t saddr, const float* g, bool pred) {
    int sz = pred ? 16 : 0;
    asm volatile("cp.async.ca.shared.global [%0], [%1], 16, %2;\n"
                 :: "r"(saddr), "l"(g), "r"(sz));
}
#define CP_COMMIT() asm volatile("cp.async.commit_group;\n" ::)
#define CP_WAIT(n)  asm volatile("cp.async.wait_group %0;\n" :: "n"(n))

__device__ __forceinline__ void atomicMaxF(float* addr, float val) {
    int* ai = (int*)addr;
    int old = *ai;
    while (__int_as_float(old) < val) {
        int assumed = old;
        old = atomicCAS(ai, assumed, __float_as_int(val));
        if (old == assumed) break;
    }
}

// ---------------- tensor-core tf32 GEMM ----------------
// A row-major [M][K] (tf32-rounded fp32). B = weights packed TRANSPOSED [N][K]
// (tf32-rounded). BM=128, BN=128, BK=32, 256 thr = 8 warps (4m x 2n), warp
// tile 32x64. cp.async double-buffered; fragments via ldmatrix.x4.
// ACT: 0 normal (bias?+resid?), 1 bias+relu, 2 fused edge message
// CVT: round output to tf32. SCORE: fuse attention score (Oe GEMM only).
#define ASZ (128 * 36)
#define BSZ (128 * 36)
#define GEMM_SMEM ((2 * ASZ + 2 * BSZ) * 4)

template <int ACT, int CVT, int SCORE>
__global__ __launch_bounds__(256, 2)
void gemm_tc(const float* __restrict__ A, const float* __restrict__ B,
             const float* __restrict__ bias, const float* __restrict__ resid,
             float* __restrict__ C, int M, int K, int N,
             const int* __restrict__ dst, const int* __restrict__ src,
             const float* __restrict__ QKV, const float* __restrict__ Aw,
             float* __restrict__ scb, float* __restrict__ smax) {
    extern __shared__ float sm[];

    const int tid = threadIdx.x;
    const int warp = tid >> 5;
    const int lane = tid & 31;
    const int g = lane >> 2;
    const int t = lane & 3;
    const int warp_m = warp & 3;
    const int warp_n = warp >> 2;
    const int m0 = blockIdx.x * 128;
    const int n0 = blockIdx.y * 128;

    const uint32_t sbase = (uint32_t)__cvta_generic_to_shared(sm);
    const uint32_t bbase = sbase + 2 * ASZ * 4;

    // staging indices (both A and B tiles are 128 rows x 32 cols)
    const int srow = tid >> 3;       // + u*32
    const int scol = (tid & 7) * 4;

    // ldmatrix per-lane address components
    const int a_row = lane & 15;
    const int a_kh  = (lane >> 4) << 2;
    const int b_row = (lane & 7) + ((lane >> 4) << 3);
    const int b_kh  = ((lane >> 3) & 1) << 2;

    float acc[2][8][4];
#pragma unroll
    for (int i = 0; i < 2; i++)
#pragma unroll
        for (int j = 0; j < 8; j++)
#pragma unroll
            for (int q = 0; q < 4; q++) acc[i][j][q] = 0.0f;

    const int KT = K >> 5;

    // prologue: stage tile 0 into buffer 0
#pragma unroll
    for (int u = 0; u < 4; u++) {
        int r = srow + u * 32;
        cp16(sbase + (r * 36 + scol) * 4, A + (size_t)(m0 + r) * K + scol, (m0 + r) < M);
        cp16(bbase + (r * 36 + scol) * 4, B + (size_t)(n0 + r) * K + scol, true);
    }
    CP_COMMIT();

    for (int kt = 0; kt < KT; kt++) {
        const int buf = kt & 1;
        if (kt + 1 < KT) {
            const int k0 = (kt + 1) << 5;
            const int nb = buf ^ 1;
#pragma unroll
            for (int u = 0; u < 4; u++) {
                int r = srow + u * 32;
                cp16(sbase + (nb * ASZ + r * 36 + scol) * 4,
                     A + (size_t)(m0 + r) * K + k0 + scol, (m0 + r) < M);
                cp16(bbase + (nb * BSZ + r * 36 + scol) * 4,
                     B + (size_t)(n0 + r) * K + k0 + scol, true);
            }
            CP_COMMIT();
            CP_WAIT(1);
        } else {
            CP_WAIT(0);
        }
        __syncthreads();

        const uint32_t abuf = sbase + buf * ASZ * 4;
        const uint32_t bbuf = bbase + buf * BSZ * 4;

#pragma unroll
        for (int ks = 0; ks < 4; ks++) {
            const int kk = ks * 8;
            uint32_t af[2][4];
#pragma unroll
            for (int i = 0; i < 2; i++) {
                int rm = warp_m * 32 + i * 16;
                ldsm4(af[i][0], af[i][1], af[i][2], af[i][3],
                      abuf + ((rm + a_row) * 36 + kk + a_kh) * 4);
            }
            uint32_t bf[8][2];
#pragma unroll
            for (int jj = 0; jj < 4; jj++) {
                int nb2 = warp_n * 64 + jj * 16;
                uint32_t r0, r1, r2, r3;
                ldsm4(r0, r1, r2, r3, bbuf + ((nb2 + b_row) * 36 + kk + b_kh) * 4);
                bf[2 * jj][0] = r0; bf[2 * jj][1] = r1;
                bf[2 * jj + 1][0] = r2; bf[2 * jj + 1][1] = r3;
            }
#pragma unroll
            for (int i = 0; i < 2; i++)
#pragma unroll
                for (int j = 0; j < 8; j++)
                    mma_tf32(acc[i][j], af[i], bf[j]);
        }
        __syncthreads();
    }

    // ---- epilogue ----
    if (ACT == 2) {
        // fused edge message: acc col pairs (even,odd) = (Ew, Eb), out col = c>>1
        float bebv[8];
        int cqv[8];
#pragma unroll
        for (int j = 0; j < 8; j++) {
            int cq = (n0 >> 1) + warp_n * 32 + j * 4 + t;
            cqv[j] = cq;
            bebv[j] = bias[cq];
        }
#pragma unroll
        for (int i = 0; i < 2; i++) {
#pragma unroll
            for (int half = 0; half < 2; half++) {
                int r = m0 + warp_m * 32 + i * 16 + half * 8 + g;
                if (r >= M) continue;
                int dn = dst[r], sn = src[r];
                const float* qrow = QKV + (size_t)dn * 768;
                const float* krow = QKV + (size_t)sn * 768 + 256;
#pragma unroll
                for (int j = 0; j < 8; j++) {
                    float ew = acc[i][j][half * 2 + 0];
                    float eb = acc[i][j][half * 2 + 1] + bebv[j];
                    float aqk = qrow[cqv[j]] + krow[cqv[j]];
                    float c1 = aqk * ew;
                    float c2 = copysignf(sqrtf(fabsf(c1)), c1);
                    float v = fmaxf(c2 + eb, 0.f);
                    C[(size_t)r * 256 + cqv[j]] = tf32r(v);
                }
            }
        }
    } else if (SCORE) {
        // Oe epilogue + fused attention score (2 heads per warp)
        const int h0 = (n0 + warp_n * 64) >> 5;
        float aw0[8], aw1[8];
#pragma unroll
        for (int j4 = 0; j4 < 4; j4++) {
            int d = j4 * 8 + 2 * t;
            aw0[2 * j4]     = __ldg(&Aw[d * 8 + h0]);
            aw0[2 * j4 + 1] = __ldg(&Aw[(d + 1) * 8 + h0]);
            aw1[2 * j4]     = __ldg(&Aw[d * 8 + h0 + 1]);
            aw1[2 * j4 + 1] = __ldg(&Aw[(d + 1) * 8 + h0 + 1]);
        }
        float2 bvj[8];
#pragma unroll
        for (int j = 0; j < 8; j++)
            bvj[j] = *(const float2*)&bias[n0 + warp_n * 64 + j * 8 + 2 * t];
#pragma unroll
        for (int i = 0; i < 2; i++) {
#pragma unroll
            for (int half = 0; half < 2; half++) {
                int r = m0 + warp_m * 32 + i * 16 + half * 8 + g;
                float s0 = 0.f, s1 = 0.f;
                if (r < M) {
#pragma unroll
                    for (int j = 0; j < 8; j++) {
                        float2 o;
                        o.x = tf32r(acc[i][j][half * 2 + 0] + bvj[j].x);
                        o.y = tf32r(acc[i][j][half * 2 + 1] + bvj[j].y);
                        int c = n0 + warp_n * 64 + j * 8 + 2 * t;
                        *(float2*)&C[(size_t)r * N + c] = o;
                        if (j < 4) {
                            s0 += o.x * aw0[2 * j] + o.y * aw0[2 * j + 1];
                        } else {
                            s1 += o.x * aw1[2 * (j - 4)] + o.y * aw1[2 * (j - 4) + 1];
                        }
                    }
                }
                s0 += __shfl_xor_sync(0xffffffffu, s0, 1);
                s0 += __shfl_xor_sync(0xffffffffu, s0, 2);
                s1 += __shfl_xor_sync(0xffffffffu, s1, 1);
                s1 += __shfl_xor_sync(0xffffffffu, s1, 2);
                if (r < M && t == 0) {
                    s0 = fminf(fmaxf(s0, -CLAMP_V), CLAMP_V);
                    s1 = fminf(fmaxf(s1, -CLAMP_V), CLAMP_V);
                    scb[(size_t)r * 8 + h0] = s0;
                    scb[(size_t)r * 8 + h0 + 1] = s1;
                    int dn = dst[r];
                    atomicMaxF(&smax[dn * 8 + h0], s0);
                    atomicMaxF(&smax[dn * 8 + h0 + 1], s1);
                }
            }
        }
    } else {
#pragma unroll
        for (int j = 0; j < 8; j++) {
            int c = n0 + warp_n * 64 + j * 8 + 2 * t;
            float2 bv = make_float2(0.f, 0.f);
            if (bias) bv = *(const float2*)&bias[c];
#pragma unroll
            for (int i = 0; i < 2; i++) {
                int rbase = m0 + warp_m * 32 + i * 16 + g;
#pragma unroll
                for (int half = 0; half < 2; half++) {
                    int r = rbase + half * 8;
                    if (r >= M) continue;
                    float2 o;
                    o.x = acc[i][j][half * 2 + 0] + bv.x;
                    o.y = acc[i][j][half * 2 + 1] + bv.y;
                    if (resid) {
                        float2 rv = *(const float2*)&resid[(size_t)r * N + c];
                        o.x += rv.x; o.y += rv.y;
                    }
                    if (ACT == 1) { o.x = fmaxf(o.x, 0.f); o.y = fmaxf(o.y, 0.f); }
                    if (CVT == 1) { o.x = tf32r(o.x); o.y = tf32r(o.y); }
                    *(float2*)&C[(size_t)r * N + c] = o;
                }
            }
        }
    }
}

// ---------------- weight pack: TRANSPOSED [N][K] + tf32 round ----------------
__global__ void pack_kernel(const float* Wq, const float* Wk, const float* Wv,
                            const float* Wew, const float* Web, const float* Weo,
                            const float* Wo_h, const float* Wo_e,
                            const float* W1, const float* W2, float* S) {
    int i = blockIdx.x * 256 + threadIdx.x;
    if (i < 196608) {  // wqkvT [768][256]
        int n = i >> 8, k = i & 255;
        float v = (n < 256) ? Wq[k * 256 + n]
                : (n < 512) ? Wk[k * 256 + n - 256]
                            : Wv[k * 256 + n - 512];
        (S + O_WQKV)[i] = tf32r(v);
    }
    int i2 = i - 196608;
    if (i2 >= 0 && i2 < 131072) {  // wewbT [512][256], rows interleaved Ew/Eb
        int n = i2 >> 8, k = i2 & 255, c = n >> 1;
        float v = (n & 1) ? Web[k * 256 + c] : Wew[k * 256 + c];
        (S + O_WEWB)[i2] = tf32r(v);
    }
    int i3 = i - 327680;
    if (i3 >= 0 && i3 < 65536) {   // weoT [256][256]
        int n = i3 >> 8, k = i3 & 255;
        (S + O_WEO)[i3] = tf32r(Weo[k * 256 + n]);
    }
    int i4 = i - 393216;
    if (i4 >= 0 && i4 < 65536) {
        int n = i4 >> 8, k = i4 & 255;
        (S + O_WOH)[i4] = tf32r(Wo_h[k * 256 + n]);
    }
    int i5 = i - 458752;
    if (i5 >= 0 && i5 < 65536) {
        int n = i5 >> 8, k = i5 & 255;
        (S + O_WOE)[i5] = tf32r(Wo_e[k * 256 + n]);
    }
    int i6 = i - 524288;
    if (i6 >= 0 && i6 < 131072) {  // w1T [512][256]
        int n = i6 >> 8, k = i6 & 255;
        (S + O_W1)[i6] = tf32r(W1[k * 512 + n]);
    }
    int i7 = i - 655360;
    if (i7 >= 0 && i7 < 131072) {  // w2T [256][512]
        int n = i7 >> 9, k = i7 & 511;
        (S + O_W2)[i7] = tf32r(W2[k * 256 + n]);
    }
}

// ---------------- tf32-round copy (float4) ----------------
__global__ void cvt_kernel(const float* __restrict__ in, float* __restrict__ out, long n4) {
    long i = (long)blockIdx.x * 256 + threadIdx.x;
    if (i >= n4) return;
    float4 v = ((const float4*)in)[i];
    v.x = tf32r(v.x); v.y = tf32r(v.y); v.z = tf32r(v.z); v.w = tf32r(v.w);
    ((float4*)out)[i] = v;
}

// ---------------- LayerNorm (optional second tf32 output) ----------------
__global__ void ln_kernel(const float* __restrict__ in, const float* __restrict__ g,
                          const float* __restrict__ b, float* __restrict__ out,
                          float* __restrict__ out_t, int M) {
    int row = blockIdx.x * 8 + (threadIdx.x >> 5);
    int lane = threadIdx.x & 31;
    if (row >= M) return;
    const float* p = in + (size_t)row * HIDC;
    float v[8];
    float s = 0.f;
#pragma unroll
    for (int i = 0; i < 8; i++) { v[i] = p[lane + i * 32]; s += v[i]; }
#pragma unroll
    for (int o = 16; o > 0; o >>= 1) s += __shfl_xor_sync(0xffffffffu, s, o);
    float mean = s * (1.0f / HIDC);
    float vs = 0.f;
#pragma unroll
    for (int i = 0; i < 8; i++) { float d = v[i] - mean; vs += d * d; }
#pragma unroll
    for (int o = 16; o > 0; o >>= 1) vs += __shfl_xor_sync(0xffffffffu, vs, o);
    float rstd = rsqrtf(vs * (1.0f / HIDC) + 1e-5f);
    float* q = out + (size_t)row * HIDC;
    float* qt = out_t ? out_t + (size_t)row * HIDC : nullptr;
#pragma unroll
    for (int i = 0; i < 8; i++) {
        int c = lane + i * 32;
        float val = (v[i] - mean) * rstd * g[c] + b[c];
        q[c] = val;
        if (qt) qt[c] = tf32r(val);
    }
}

// ---------------- init ----------------
__global__ void init_kernel(float* agg, float* rowv, float* smax, float* ssum, int Nn) {
    int t = blockIdx.x * 256 + threadIdx.x;
    if (t < Nn * HIDC) { agg[t] = 0.f; rowv[t] = 0.f; }
    if (t < Nn * NHEAD) { smax[t] = -CLAMP_V; ssum[t] = 0.f; }
}

// ---------------- exp + segment sum ----------------
__global__ void ex_kernel(float* __restrict__ score, const float* __restrict__ smax,
                          float* __restrict__ ssum, const int* __restrict__ dst, int E) {
    int t = blockIdx.x * 256 + threadIdx.x;
    if (t >= E * NHEAD) return;
    int e = t >> 3, h = t & 7;
    int dn = dst[e];
    float ex = expf(score[t] - smax[dn * NHEAD + h]);
    score[t] = ex;
    atomicAdd(&ssum[dn * NHEAD + h], ex);
}

// ---------------- scatter (V rows in QKV, col offset 512, stride 768) ----------------
__global__ void scatter_kernel(const float* __restrict__ exv, const float* __restrict__ ssum,
                               const float* __restrict__ QKV, const float* __restrict__ Oe,
                               float* __restrict__ agg, float* __restrict__ rowv,
                               const int* __restrict__ dst, const int* __restrict__ src, int E) {
    long t = (long)blockIdx.x * 256 + threadIdx.x;
    if (t >= (long)E * 64) return;
    int e = (int)(t >> 6), q = (int)(t & 63);
    int h = q >> 3;
    int dn = dst[e], sn = src[e];
    float sc = exv[e * NHEAD + h] / (ssum[dn * NHEAD + h] + 1e-16f);
    float4 v = *(const float4*)&QKV[(size_t)sn * 768 + 512 + q * 4];
    float4 o = *(const float4*)&Oe[(size_t)e * HIDC + q * 4];
    float* ap = &agg[(size_t)dn * HIDC + q * 4];
    atomicAdd(ap + 0, v.x * sc); atomicAdd(ap + 1, v.y * sc);
    atomicAdd(ap + 2, v.z * sc); atomicAdd(ap + 3, v.w * sc);
    float* rp = &rowv[(size_t)dn * HIDC + q * 4];
    atomicAdd(rp + 0, o.x * sc); atomicAdd(rp + 1, o.y * sc);
    atomicAdd(rp + 2, o.z * sc); atomicAdd(rp + 3, o.w * sc);
}

// ---------------- combine: On = tf32(agg + einsum(rowv, BW)) ----------------
__global__ void combine_kernel(const float* __restrict__ agg, const float* __restrict__ rowv,
                               const float* __restrict__ BW, float* __restrict__ On, int Nn) {
    __shared__ float sBW[32 * 8 * 32];
    __shared__ float srv[HIDC];
    int tid = threadIdx.x;
    for (int i = tid; i < 32 * 8 * 32; i += 256) sBW[i] = BW[i];
    int h = tid >> 5, c = tid & 31;
    for (int r = 0; r < 4; r++) {
        int n = blockIdx.x * 4 + r;
        __syncthreads();
        if (n < Nn) srv[tid] = rowv[(size_t)n * HIDC + tid];
        __syncthreads();
        if (n < Nn) {
            float s = agg[(size_t)n * HIDC + tid];
#pragma unroll
            for (int d = 0; d < 32; d++)
                s += srv[h * 32 + d] * sBW[d * HIDC + h * 32 + c];
            On[(size_t)n * HIDC + tid] = tf32r(s);
        }
    }
}

// ---------------- launch ----------------
extern "C" void kernel_launch(void* const* d_in, const int* in_sizes, int n_in,
                              void* d_out, int out_size) {
    const float* x     = (const float*)d_in[0];
    const float* conn  = (const float*)d_in[1];
    const float* Wq    = (const float*)d_in[2];
    const float* Wk    = (const float*)d_in[3];
    const float* Wv    = (const float*)d_in[4];
    const float* Wew   = (const float*)d_in[5];
    const float* Web   = (const float*)d_in[6];
    const float* beb   = (const float*)d_in[7];
    const float* Weo   = (const float*)d_in[8];
    const float* beo   = (const float*)d_in[9];
    const float* Aw    = (const float*)d_in[10];
    const float* BW    = (const float*)d_in[11];
    const float* Wo_h  = (const float*)d_in[12];
    const float* bo_h  = (const float*)d_in[13];
    const float* Wo_e  = (const float*)d_in[14];
    const float* bo_e  = (const float*)d_in[15];
    const float* ln1hg = (const float*)d_in[16];
    const float* ln1hb = (const float*)d_in[17];
    const float* ln1eg = (const float*)d_in[18];
    const float* ln1eb = (const float*)d_in[19];
    const float* W1    = (const float*)d_in[20];
    const float* b1    = (const float*)d_in[21];
    const float* W2    = (const float*)d_in[22];
    const float* b2    = (const float*)d_in[23];
    const float* ln2hg = (const float*)d_in[24];
    const float* ln2hb = (const float*)d_in[25];
    const int*   ei    = (const int*)d_in[26];

    int Nn = in_sizes[0] / HIDC;
    int Ee = in_sizes[26] / 2;
    const int* dst = ei;
    const int* src = ei + Ee;

    float* S = nullptr;
    cudaGetSymbolAddress((void**)&S, g_scratch);

    float* QKV  = S + O_QKV;
    float* cA   = S + O_CA;
    float* Oe   = S + O_OE;
    float* scb  = S + O_SCB;
    float* smax = S + O_SMAX;
    float* ssum = S + O_SSUM;
    float* agg  = S + O_AGG;
    float* rowv = S + O_ROWV;
    float* On   = S + O_ON;
    float* h1   = S + O_H1;
    float* hln  = S + O_HLN;
    float* hlnt = S + O_HLNT;
    float* ffn  = S + O_FFN;
    float* h2   = S + O_H2;
    float* xt   = S + O_XT;
    float* ct   = S + O_CT;

    float* outH = (float*)d_out;
    float* outE = outH + (size_t)Nn * HIDC;

    cudaFuncSetAttribute(gemm_tc<0, 0, 0>, cudaFuncAttributeMaxDynamicSharedMemorySize, GEMM_SMEM);
    cudaFuncSetAttribute(gemm_tc<0, 1, 1>, cudaFuncAttributeMaxDynamicSharedMemorySize, GEMM_SMEM);
    cudaFuncSetAttribute(gemm_tc<1, 1, 0>, cudaFuncAttributeMaxDynamicSharedMemorySize, GEMM_SMEM);
    cudaFuncSetAttribute(gemm_tc<2, 0, 0>, cudaFuncAttributeMaxDynamicSharedMemorySize, GEMM_SMEM);

    // prep
    pack_kernel<<<cdiv(786432, 256), 256>>>(Wq, Wk, Wv, Wew, Web, Weo, Wo_h, Wo_e, W1, W2, S);
    cvt_kernel<<<cdiv(Nn * 64, 256), 256>>>(x, xt, (long)Nn * 64);
    cvt_kernel<<<(int)cdiv((long)Ee * 64, 256), 256>>>(conn, ct, (long)Ee * 64);
    init_kernel<<<cdiv(Nn * HIDC, 256), 256>>>(agg, rowv, smax, ssum, Nn);

    // QKV = xt @ Wqkv  [N, 768]
    {
        dim3 g(cdiv(Nn, 128), 6);
        gemm_tc<0, 0, 0><<<g, 256, GEMM_SMEM>>>(xt, S + O_WQKV, nullptr, nullptr, QKV,
                                                Nn, 256, 768, nullptr, nullptr, nullptr,
                                                nullptr, nullptr, nullptr);
    }
    // fused: EwEb GEMM + edge message -> cA (tf32)
    {
        dim3 g(cdiv(Ee, 128), 4);
        gemm_tc<2, 0, 0><<<g, 256, GEMM_SMEM>>>(ct, S + O_WEWB, beb, nullptr, cA,
                                                Ee, 256, 512, dst, src, QKV,
                                                nullptr, nullptr, nullptr);
    }
    // Oe = cA @ Weo + beo (tf32 out) + fused score/clamp/segment-max
    {
        dim3 g(cdiv(Ee, 128), 2);
        gemm_tc<0, 1, 1><<<g, 256, GEMM_SMEM>>>(cA, S + O_WEO, beo, nullptr, Oe,
                                                Ee, 256, 256, dst, nullptr, nullptr,
                                                Aw, scb, smax);
    }

    ex_kernel<<<cdiv(Ee * NHEAD, 256), 256>>>(scb, smax, ssum, dst, Ee);
    scatter_kernel<<<(int)cdiv((long)Ee * 64, 256), 256>>>(scb, ssum, QKV, Oe, agg, rowv, dst, src, Ee);
    combine_kernel<<<cdiv(Nn, 4), 256>>>(agg, rowv, BW, On, Nn);

    // h path
    {
        dim3 g(cdiv(Nn, 128), 2);
        gemm_tc<0, 0, 0><<<g, 256, GEMM_SMEM>>>(On, S + O_WOH, bo_h, x, h1,
                                                Nn, 256, 256, nullptr, nullptr, nullptr,
                                                nullptr, nullptr, nullptr);
    }
    ln_kernel<<<cdiv(Nn, 8), 256>>>(h1, ln1hg, ln1hb, hln, hlnt, Nn);

    // e path
    {
        dim3 g(cdiv(Ee, 128), 2);
        gemm_tc<0, 0, 0><<<g, 256, GEMM_SMEM>>>(Oe, S + O_WOE, bo_e, conn, cA,
                                                Ee, 256, 256, nullptr, nullptr, nullptr,
                                                nullptr, nullptr, nullptr);
    }
    ln_kernel<<<cdiv(Ee, 8), 256>>>(cA, ln1eg, ln1eb, outE, nullptr, Ee);

    // FFN
    {
        dim3 g(cdiv(Nn, 128), 4);
        gemm_tc<1, 1, 0><<<g, 256, GEMM_SMEM>>>(hlnt, S + O_W1, b1, nullptr, ffn,
                                                Nn, 256, 512, nullptr, nullptr, nullptr,
                                                nullptr, nullptr, nullptr);
    }
    {
        dim3 g(cdiv(Nn, 128), 2);
        gemm_tc<0, 0, 0><<<g, 256, GEMM_SMEM>>>(ffn, S + O_W2, b2, hln, h2,
                                                Nn, 512, 256, nullptr, nullptr, nullptr,
                                                nullptr, nullptr, nullptr);
    }
    ln_kernel<<<cdiv(Nn, 8), 256>>>(h2, ln2hg, ln2hb, outH, nullptr, Nn);
}